// round 12
// baseline (speedup 1.0000x reference)
#include <cuda_runtime.h>
#include <cuda_fp16.h>
#include <cstdint>

#define NB_B   2
#define NB     512
#define LQ     64
#define KEYN   65
#define NH     8
#define HD     64
#define CDIM   512
#define NTOK   32768
#define BNB    (NB_B*NB)        // 1024 blocks total
#define MX     (NB_B*NTOK)      // 65536 x-rows
#define KVROWS (BNB*KEYN)       // 66560 kv-rows
#define MTILES (MX/128)         // 512

// -------- device scratch (static, allocation-guard safe) --------
__device__ __half g_biasadd[(size_t)BNB*4160];   // fp16 pre-masked additive bias
__device__ __half g_lewh[(size_t)BNB*NH*4160];   // fp16 lew
__device__ __half g_xh [(size_t)MX*CDIM];        // fp16 x
__device__ __half g_wqh[(size_t)3*CDIM*CDIM];    // fp16 qkv_w
__device__ __half g_wph[(size_t)CDIM*CDIM];      // fp16 proj_w
__device__ __half g_bmh[(size_t)BNB*CDIM];       // fp16 block means
__device__ __half g_qh [(size_t)MX*CDIM];        // fp16 q
__device__ __half g_kh [(size_t)KVROWS*CDIM];    // fp16 k
__device__ __half g_vh [(size_t)KVROWS*CDIM];    // fp16 v
__device__ __half g_atth[(size_t)MX*CDIM];       // fp16 attention output

// ================= fp32 -> fp16 conversion (weights only) =================
__global__ void conv_h(const float4* __restrict__ src, __half2* __restrict__ dst, int n4) {
    int i = blockIdx.x * blockDim.x + threadIdx.x;
    if (i < n4) {
        float4 v = src[i];
        dst[2 * i]     = __floats2half2_rn(v.x, v.y);
        dst[2 * i + 1] = __floats2half2_rn(v.z, v.w);
    }
}

// ======== block mean + x->fp16 in one pass over x ========
__global__ void mean_conv_kernel(const float* __restrict__ x) {
    int blk = blockIdx.x;
    const float* base = x + (size_t)blk * (LQ * CDIM);
    __half* xout = g_xh + (size_t)blk * (LQ * CDIM);
    for (int c = threadIdx.x; c < CDIM; c += blockDim.x) {
        float s = 0.f;
        #pragma unroll 8
        for (int l = 0; l < LQ; l++) {
            float v = base[(size_t)l * CDIM + c];
            s += v;
            xout[(size_t)l * CDIM + c] = __float2half_rn(v);
        }
        g_bmh[(size_t)blk * CDIM + c] = __float2half_rn(s * (1.f / 64.f));
    }
}

// ================= prep: fold mask into bias, precompute lew =================
__global__ void __launch_bounds__(256) prep_kernel(const float* __restrict__ edge,
                                                   const int* __restrict__ amask,
                                                   const float* __restrict__ eg_w,
                                                   const float* __restrict__ eg_b) {
    int bid = blockIdx.x;
    int base = blockIdx.y * 2080;
    const float4* e4 = reinterpret_cast<const float4*>(edge) + (size_t)bid * 4160;
    const int* mk = amask + (size_t)bid * 4160;
    float w[NH][4], b[NH];
    #pragma unroll
    for (int h = 0; h < NH; h++) {
        w[h][0] = eg_w[h * 4 + 0]; w[h][1] = eg_w[h * 4 + 1];
        w[h][2] = eg_w[h * 4 + 2]; w[h][3] = eg_w[h * 4 + 3];
        b[h] = eg_b[h];
    }
    for (int i = base + threadIdx.x; i < base + 2080; i += 256) {
        int q = i / 65;
        int k = i - q * 65;
        float4 e = e4[i];
        if (k == 64 || k == q) e = make_float4(0.f, 0.f, 0.f, 1.f);
        bool m = (mk[i] != 0);
        g_biasadd[(size_t)bid * 4160 + i] = __float2half_rn(m ? e.w : -30000.f);
        #pragma unroll
        for (int h = 0; h < NH; h++) {
            float lv = e.x * w[h][0] + e.y * w[h][1] + e.z * w[h][2] + e.w * w[h][3] + b[h];
            g_lewh[((size_t)bid * NH + h) * 4160 + i] = __float2half_rn(m ? lv : 0.f);
        }
    }
}

// ================= mma / ldmatrix helpers =================
__device__ __forceinline__ void mma_f16(float* c, const uint32_t* a, const uint32_t* b) {
    asm volatile(
        "mma.sync.aligned.m16n8k16.row.col.f32.f16.f16.f32 "
        "{%0,%1,%2,%3}, {%4,%5,%6,%7}, {%8,%9}, {%0,%1,%2,%3};\n"
        : "+f"(c[0]), "+f"(c[1]), "+f"(c[2]), "+f"(c[3])
        : "r"(a[0]), "r"(a[1]), "r"(a[2]), "r"(a[3]),
          "r"(b[0]), "r"(b[1]));
}

__device__ __forceinline__ void ldsm4(uint32_t* r, uint32_t addr) {
    asm volatile("ldmatrix.sync.aligned.m8n8.x4.shared.b16 {%0,%1,%2,%3}, [%4];"
                 : "=r"(r[0]), "=r"(r[1]), "=r"(r[2]), "=r"(r[3]) : "r"(addr));
}

__device__ __forceinline__ void ldsm4t(uint32_t* r, uint32_t addr) {
    asm volatile("ldmatrix.sync.aligned.m8n8.x4.trans.shared.b16 {%0,%1,%2,%3}, [%4];"
                 : "=r"(r[0]), "=r"(r[1]), "=r"(r[2]), "=r"(r[3]) : "r"(addr));
}

__device__ __forceinline__ void cp16(uint32_t smem_dst, const __half* gmem_src) {
    asm volatile("cp.async.cg.shared.global [%0], [%1], 16;\n"
                 :: "r"(smem_dst), "l"(gmem_src));
}

// epilogue scatter (column pairs). MODE 0 = fused qkv (+ block-node rows), MODE 2 = proj.
template <int MODE>
__device__ __forceinline__ void emit2(bool bm, int row, int col, float v0, float v1, float* outp) {
    if (MODE == 2) {
        float2 f = make_float2(v0, v1);
        *reinterpret_cast<float2*>(&outp[(size_t)row * CDIM + col]) = f;
    } else {
        __half2 hv = __floats2half2_rn(v0, v1);
        if (!bm) {
            if (col < CDIM) {
                *reinterpret_cast<__half2*>(&g_qh[(size_t)row * CDIM + col]) = hv;
            } else {
                size_t kvr = (size_t)((row >> 6) * KEYN + (row & 63));
                if (col < 2 * CDIM)
                    *reinterpret_cast<__half2*>(&g_kh[kvr * CDIM + (col - CDIM)]) = hv;
                else
                    *reinterpret_cast<__half2*>(&g_vh[kvr * CDIM + (col - 2 * CDIM)]) = hv;
            }
        } else {
            size_t r = (size_t)row * KEYN + (KEYN - 1);
            if (col < 2 * CDIM) *reinterpret_cast<__half2*>(&g_kh[r * CDIM + (col - CDIM)]) = hv;
            else                *reinterpret_cast<__half2*>(&g_vh[r * CDIM + (col - 2 * CDIM)]) = hv;
        }
    }
}

// ================= fp16 GEMM: C = A[M,512] * W[N,512]^T + bias =================
// CTA tile 128x128, 128 threads = 4 warps (2x2), warp tile 64x64.
// k-tile 64 halves, 3-stage cp.async pipeline, 2 CTAs/SM.
// MODE 0: grid.y in [0, MTILES+8): last 8 m-tiles compute block-node k/v from g_bmh.
#define GH_STAGE  (128 * 72)
#define GH_B_OFF  (3 * GH_STAGE)
#define GEMM_SMEM_BYTES (6 * GH_STAGE * 2)   // 110592 B

template <int MODE>
__global__ void __launch_bounds__(128, 2) gemm_h(const __half* __restrict__ Ain,
                                                 const __half* __restrict__ W,
                                                 const float* __restrict__ bias,
                                                 float* __restrict__ outp) {
    extern __shared__ __align__(16) __half hsm[];
    uint32_t smem_u32 = (uint32_t)__cvta_generic_to_shared(hsm);

    int tid = threadIdx.x;
    int n0 = blockIdx.x * 128;
    int by = blockIdx.y;

    bool bm = false;
    const __half* A;
    int m0;
    if (MODE == 0) {
        bm = (by >= MTILES);
        if (bm && n0 < CDIM) return;     // block-node rows have no q columns
        A = bm ? g_bmh : Ain;
        m0 = bm ? (by - MTILES) * 128 : by * 128;
    } else {
        A = g_atth;
        m0 = by * 128;
    }

    int lane = tid & 31, wid = tid >> 5;
    int wm = wid >> 1, wn = wid & 1;
    int g = lane >> 2, t4 = lane & 3;

    int a_term = (wm * 64 + (lane & 15)) * 72 + (lane >> 4) * 8;
    int b_term = (wn * 64 + (lane >> 4) * 8 + (lane & 7)) * 72 + ((lane >> 3) & 1) * 8;

    float acc[4][8][4];
    #pragma unroll
    for (int mi = 0; mi < 4; mi++)
        #pragma unroll
        for (int ni = 0; ni < 8; ni++)
            #pragma unroll
            for (int r = 0; r < 4; r++) acc[mi][ni][r] = 0.f;

    auto fill = [&](int k0, int st) {
        #pragma unroll
        for (int i = 0; i < 8; i++) {
            int o = tid + 128 * i;
            int row = o >> 3, seg = o & 7;
            uint32_t doff = (uint32_t)(st * GH_STAGE + row * 72 + seg * 8) * 2u;
            cp16(smem_u32 + doff, &A[(size_t)(m0 + row) * CDIM + k0 + seg * 8]);
            cp16(smem_u32 + (uint32_t)GH_B_OFF * 2u + doff,
                 &W[(size_t)(n0 + row) * CDIM + k0 + seg * 8]);
        }
        asm volatile("cp.async.commit_group;\n");
    };

    fill(0, 0);
    fill(64, 1);
    for (int j = 0; j < 8; j++) {
        if (j < 7) asm volatile("cp.async.wait_group 1;\n");
        else       asm volatile("cp.async.wait_group 0;\n");
        __syncthreads();
        if (j + 2 < 8) fill((j + 2) * 64, (j + 2) % 3);

        int st = (j % 3) * GH_STAGE;
        uint32_t a_base = smem_u32 + (uint32_t)(st + a_term) * 2u;
        uint32_t b_base = smem_u32 + (uint32_t)(GH_B_OFF + st + b_term) * 2u;
        #pragma unroll
        for (int kk = 0; kk < 64; kk += 16) {
            uint32_t afr[4][4], bfr[8][2];
            #pragma unroll
            for (int mi = 0; mi < 4; mi++)
                ldsm4(afr[mi], a_base + (uint32_t)(mi * 16 * 72 + kk) * 2u);
            #pragma unroll
            for (int jp = 0; jp < 4; jp++) {
                uint32_t bb[4];
                ldsm4(bb, b_base + (uint32_t)(jp * 16 * 72 + kk) * 2u);
                bfr[2 * jp][0] = bb[0]; bfr[2 * jp][1] = bb[1];
                bfr[2 * jp + 1][0] = bb[2]; bfr[2 * jp + 1][1] = bb[3];
            }
            #pragma unroll
            for (int mi = 0; mi < 4; mi++)
                #pragma unroll
                for (int ni = 0; ni < 8; ni++)
                    mma_f16(acc[mi][ni], afr[mi], bfr[ni]);
        }
    }

    #pragma unroll
    for (int mi = 0; mi < 4; mi++) {
        #pragma unroll
        for (int ni = 0; ni < 8; ni++) {
            int row = m0 + wm * 64 + mi * 16 + g;
            int col = n0 + wn * 64 + ni * 8 + t4 * 2;
            float b0 = bias[col], b1 = bias[col + 1];
            emit2<MODE>(bm, row,     col, acc[mi][ni][0] + b0, acc[mi][ni][1] + b1, outp);
            emit2<MODE>(bm, row + 8, col, acc[mi][ni][2] + b0, acc[mi][ni][3] + b1, outp);
        }
    }
}

// ================= attention: tensor-core, one CTA per (block, head) ==========
// 128 threads (4 warps). P stays in registers; V fed via ldmatrix.trans.
// smem bytes:
//   ba   fp16 4160        @0      (8320)
//   q    fp16 64x72       @8320   (9216)
//   k    fp16 80x72       @17536  (11520)  rows 65..79 zero
//   v    fp16 80x72       @29056  (11520)  rows 65..79 zero (row-major [key][d])
#define AT_SMEM_BYTES 40576

__global__ void __launch_bounds__(128, 5) attn_kernel() {
    extern __shared__ char smc[];
    __half* ba_s = reinterpret_cast<__half*>(smc);
    __half* q_s  = reinterpret_cast<__half*>(smc + 8320);
    __half* k_s  = reinterpret_cast<__half*>(smc + 17536);
    __half* v_s  = reinterpret_cast<__half*>(smc + 29056);

    int bid = blockIdx.x;      // 0..1023
    int h   = blockIdx.y;      // 0..7
    int tid = threadIdx.x;

    {
        const uint32_t* src = reinterpret_cast<const uint32_t*>(g_biasadd + (size_t)bid * 4160);
        uint32_t* dst = reinterpret_cast<uint32_t*>(ba_s);
        for (int i = tid; i < 2080; i += 128) dst[i] = src[i];
    }
    const __half2* qg = reinterpret_cast<const __half2*>(g_qh + (size_t)(bid * 64) * CDIM + h * 64);
    for (int i = tid; i < 64 * 32; i += 128) {
        int row = i >> 5, c = i & 31;
        *reinterpret_cast<__half2*>(&q_s[row * 72 + c * 2]) = qg[row * 256 + c];
    }
    const __half2* kg = reinterpret_cast<const __half2*>(g_kh + (size_t)(bid * 65) * CDIM + h * 64);
    const __half2* vg = reinterpret_cast<const __half2*>(g_vh + (size_t)(bid * 65) * CDIM + h * 64);
    for (int i = tid; i < 65 * 32; i += 128) {
        int row = i >> 5, c = i & 31;
        *reinterpret_cast<__half2*>(&k_s[row * 72 + c * 2]) = kg[row * 256 + c];
        *reinterpret_cast<__half2*>(&v_s[row * 72 + c * 2]) = vg[row * 256 + c];
    }
    for (int i = tid; i < 540; i += 128) {
        reinterpret_cast<uint32_t*>(k_s + 65 * 72)[i] = 0u;
        reinterpret_cast<uint32_t*>(v_s + 65 * 72)[i] = 0u;
    }
    __syncthreads();

    int lane = tid & 31, w = tid >> 5;
    int g = lane >> 2, t4 = lane & 3;
    int r0 = w * 16;

    uint32_t q_u32 = (uint32_t)__cvta_generic_to_shared(q_s);
    uint32_t k_u32 = (uint32_t)__cvta_generic_to_shared(k_s);
    uint32_t v_u32 = (uint32_t)__cvta_generic_to_shared(v_s);

    uint32_t qa_base = q_u32 + (uint32_t)(((r0 + (lane & 15)) * 72 + (lane >> 4) * 8) * 2);
    uint32_t kb_term = (uint32_t)((((lane >> 4) * 8 + (lane & 7)) * 72 + ((lane >> 3) & 1) * 8) * 2);
    uint32_t vb_term = (uint32_t)(((lane & 15) * 72 + (lane >> 4) * 8) * 2);

    // ---- scores: S[r0..r0+15][0..79] ----
    float acc[10][4];
    #pragma unroll
    for (int nt = 0; nt < 10; nt++)
        #pragma unroll
        for (int r = 0; r < 4; r++) acc[nt][r] = 0.f;

    #pragma unroll
    for (int kst = 0; kst < 4; kst++) {
        uint32_t a[4];
        ldsm4(a, qa_base + (uint32_t)(kst * 16 * 2));
        #pragma unroll
        for (int jp = 0; jp < 5; jp++) {
            uint32_t bb[4];
            ldsm4(bb, k_u32 + kb_term + (uint32_t)((jp * 16 * 72 + kst * 16) * 2));
            mma_f16(acc[2 * jp], a, bb);
            mma_f16(acc[2 * jp + 1], a, bb + 2);
        }
    }

    // ---- softmax + lew on fragments; P packed straight into registers ----
    const __half* lewp = g_lewh + ((size_t)bid * NH + h) * 4160;
    uint32_t ph[2][10];
    #pragma unroll
    for (int rr = 0; rr < 2; rr++) {
        int row = r0 + g + rr * 8;
        float mx = -1e30f;
        #pragma unroll
        for (int nt = 0; nt < 10; nt++) {
            #pragma unroll
            for (int e = 0; e < 2; e++) {
                int col = nt * 8 + t4 * 2 + e;
                float s = (col < 65) ? fmaf(acc[nt][rr * 2 + e], 0.125f,
                                            __half2float(ba_s[row * 65 + col]))
                                     : -1e30f;
                acc[nt][rr * 2 + e] = s;
                mx = fmaxf(mx, s);
            }
        }
        mx = fmaxf(mx, __shfl_xor_sync(0xffffffffu, mx, 1));
        mx = fmaxf(mx, __shfl_xor_sync(0xffffffffu, mx, 2));
        float sum = 0.f;
        #pragma unroll
        for (int nt = 0; nt < 10; nt++) {
            #pragma unroll
            for (int e = 0; e < 2; e++) {
                float p = __expf(acc[nt][rr * 2 + e] - mx);
                acc[nt][rr * 2 + e] = p;
                sum += p;
            }
        }
        sum += __shfl_xor_sync(0xffffffffu, sum, 1);
        sum += __shfl_xor_sync(0xffffffffu, sum, 2);
        float inv = 1.f / sum;
        #pragma unroll
        for (int nt = 0; nt < 10; nt++) {
            int col = nt * 8 + t4 * 2;
            float c0 = (col < 65)     ? fmaf(acc[nt][rr * 2],     inv, __half2float(__ldg(&lewp[row * 65 + col])))     : 0.f;
            float c1 = (col + 1 < 65) ? fmaf(acc[nt][rr * 2 + 1], inv, __half2float(__ldg(&lewp[row * 65 + col + 1]))) : 0.f;
            __half2 t = __floats2half2_rn(c0, c1);
            ph[rr][nt] = *reinterpret_cast<uint32_t*>(&t);
        }
    }

    // ---- AV: O[r0..r0+15][0..63] = P[.,0..79] x V[0..79,.] (B via ldmatrix.trans) ----
    float oc[8][4];
    #pragma unroll
    for (int nt = 0; nt < 8; nt++)
        #pragma unroll
        for (int r = 0; r < 4; r++) oc[nt][r] = 0.f;

    #pragma unroll
    for (int kst = 0; kst < 5; kst++) {
        uint32_t a2[4] = { ph[0][2 * kst], ph[1][2 * kst],
                           ph[0][2 * kst + 1], ph[1][2 * kst + 1] };
        #pragma unroll
        for (int jp = 0; jp < 4; jp++) {
            uint32_t bb[4];
            ldsm4t(bb, v_u32 + vb_term + (uint32_t)((kst * 16 * 72 + jp * 16) * 2));
            mma_f16(oc[2 * jp], a2, bb);
            mma_f16(oc[2 * jp + 1], a2, bb + 2);
        }
    }

    __half* og = g_atth + (size_t)(bid * 64) * CDIM + h * 64;
    #pragma unroll
    for (int nt = 0; nt < 8; nt++) {
        int col = nt * 8 + t4 * 2;
        *reinterpret_cast<__half2*>(&og[(size_t)(r0 + g) * CDIM + col]) =
            __floats2half2_rn(oc[nt][0], oc[nt][1]);
        *reinterpret_cast<__half2*>(&og[(size_t)(r0 + g + 8) * CDIM + col]) =
            __floats2half2_rn(oc[nt][2], oc[nt][3]);
    }
}

// ================= host =================
extern "C" void kernel_launch(void* const* d_in, const int* in_sizes, int n_in,
                              void* d_out, int out_size) {
    (void)in_sizes; (void)n_in; (void)out_size;
    const float* x      = (const float*)d_in[0];
    const int*   amask  = (const int*)d_in[1];
    const float* edge   = (const float*)d_in[2];
    const float* qkv_w  = (const float*)d_in[3];
    const float* qkv_b  = (const float*)d_in[4];
    const float* proj_w = (const float*)d_in[5];
    const float* proj_b = (const float*)d_in[6];
    const float* eg_w   = (const float*)d_in[7];
    const float* eg_b   = (const float*)d_in[8];
    float* out = (float*)d_out;

    // one-time setup (no device allocations; streams/events created on the
    // correctness call, reused verbatim during graph capture)
    static cudaStream_t s2 = nullptr;
    static cudaEvent_t ev_fork = nullptr, ev_join = nullptr;
    if (s2 == nullptr) {
        cudaStreamCreateWithFlags(&s2, cudaStreamNonBlocking);
        cudaEventCreateWithFlags(&ev_fork, cudaEventDisableTiming);
        cudaEventCreateWithFlags(&ev_join, cudaEventDisableTiming);
        cudaFuncSetAttribute(attn_kernel, cudaFuncAttributeMaxDynamicSharedMemorySize, AT_SMEM_BYTES);
        cudaFuncSetAttribute(gemm_h<0>, cudaFuncAttributeMaxDynamicSharedMemorySize, GEMM_SMEM_BYTES);
        cudaFuncSetAttribute(gemm_h<2>, cudaFuncAttributeMaxDynamicSharedMemorySize, GEMM_SMEM_BYTES);
    }

    __half* d_xh;  cudaGetSymbolAddress((void**)&d_xh,  g_xh);
    __half* d_wqh; cudaGetSymbolAddress((void**)&d_wqh, g_wqh);
    __half* d_wph; cudaGetSymbolAddress((void**)&d_wph, g_wph);

    // fork: prep + proj-weight conversion run concurrently with the qkv path
    cudaEventRecord(ev_fork, 0);
    cudaStreamWaitEvent(s2, ev_fork, 0);
    conv_h<<<(CDIM * CDIM / 4 + 255) / 256, 256, 0, s2>>>((const float4*)proj_w, (__half2*)d_wph, CDIM * CDIM / 4);
    prep_kernel<<<dim3(BNB, 2), 256, 0, s2>>>(edge, amask, eg_w, eg_b);
    cudaEventRecord(ev_join, s2);

    // main: qkv path
    conv_h<<<(3 * CDIM * CDIM / 4 + 255) / 256, 256>>>((const float4*)qkv_w, (__half2*)d_wqh, 3 * CDIM * CDIM / 4);
    mean_conv_kernel<<<BNB, 256>>>(x);
    // fused QKV GEMM: leaf rows (512 m-tiles) + block-node rows (8 m-tiles)
    gemm_h<0><<<dim3(1536 / 128, MTILES + 8), 128, GEMM_SMEM_BYTES>>>(d_xh, d_wqh, qkv_b, nullptr);

    cudaStreamWaitEvent(0, ev_join, 0);
    attn_kernel<<<dim3(BNB, NH), 128, AT_SMEM_BYTES>>>();
    gemm_h<2><<<dim3(512 / 128, MX / 128), 128, GEMM_SMEM_BYTES>>>(nullptr, d_wph, proj_b, out);
}